// round 13
// baseline (speedup 1.0000x reference)
#include <cuda_runtime.h>
#include <cuda_bf16.h>
#include <cstdint>

#define NROWS 8192
#define NCODES 8192
#define HID 256
#define EPS 1.0f
#define MAXC 256
#define NTILE 64                      // NCODES / 128

typedef unsigned long long u64;

// ---------------------------------------------------------------------------
// Device scratch (static globals — allocation-free)
// ---------------------------------------------------------------------------
__device__ __align__(16) __nv_bfloat16 g_hbf[NROWS * HID];
__device__ __align__(16) __nv_bfloat16 g_cbf[NCODES * HID];
__device__ float g_hsq[NROWS];
__device__ float g_csq[NCODES];
__device__ __align__(16) __nv_bfloat16 g_score[(size_t)NROWS * NCODES];  // 128 MB
__device__ float g_tmin[NTILE * NROWS];                                  // 2 MB, [tile][row]

__device__ __forceinline__ uint32_t smem_u32(const void* p) {
    uint32_t a;
    asm("{ .reg .u64 t; cvta.to.shared.u64 t, %1; cvt.u32.u64 %0, t; }"
        : "=r"(a) : "l"(p));
    return a;
}
__device__ __forceinline__ void cp16(uint32_t dst, const void* src) {
    asm volatile("cp.async.cg.shared.global [%0], [%1], 16;" :: "r"(dst), "l"(src));
}
#define CP_COMMIT() asm volatile("cp.async.commit_group;" ::: "memory")
#define CP_WAIT0()  asm volatile("cp.async.wait_group 0;"  ::: "memory")
#define CP_WAIT1()  asm volatile("cp.async.wait_group 1;"  ::: "memory")

#define LDSM_X4(r0, r1, r2, r3, addr)                                          \
    asm volatile("ldmatrix.sync.aligned.m8n8.x4.shared.b16 {%0,%1,%2,%3}, [%4];" \
                 : "=r"(r0), "=r"(r1), "=r"(r2), "=r"(r3) : "r"(addr))

#define MMA16816(d, a0, a1, a2, a3, b0, b1)                                    \
    asm volatile(                                                              \
        "mma.sync.aligned.m16n8k16.row.col.f32.bf16.bf16.f32 "                 \
        "{%0,%1,%2,%3}, {%4,%5,%6,%7}, {%8,%9}, {%0,%1,%2,%3};"                \
        : "+f"((d)[0]), "+f"((d)[1]), "+f"((d)[2]), "+f"((d)[3])               \
        : "r"(a0), "r"(a1), "r"(a2), "r"(a3), "r"(b0), "r"(b1))

// order-preserving float<->uint map
__device__ __forceinline__ unsigned enc_f(float f) {
    unsigned u = __float_as_uint(f);
    return (u & 0x80000000u) ? ~u : (u | 0x80000000u);
}
__device__ __forceinline__ float dec_f(unsigned e) {
    unsigned u = (e & 0x80000000u) ? (e ^ 0x80000000u) : ~e;
    return __uint_as_float(u);
}

// ---------------------------------------------------------------------------
// Zero-fill of the one-hot region (runs on a forked stream under the GEMM)
// ---------------------------------------------------------------------------
__global__ void zero_out_kernel(float* __restrict__ out) {
    const size_t total16 = (size_t)NROWS * NCODES / 4;   // uint4 count
    size_t i = (size_t)blockIdx.x * blockDim.x + threadIdx.x;
    const size_t stride = (size_t)gridDim.x * blockDim.x;
    uint4 z = make_uint4(0, 0, 0, 0);
    for (; i < total16; i += stride) ((uint4*)out)[i] = z;
}

// ---------------------------------------------------------------------------
// Fused fp32->bf16 convert + squared norms (one warp per row)
// ---------------------------------------------------------------------------
__global__ void convert_norms_kernel(const float* __restrict__ h,
                                     const float* __restrict__ cb) {
    int warp = (blockIdx.x * blockDim.x + threadIdx.x) >> 5;
    int lane = threadIdx.x & 31;
    const float* src;
    __nv_bfloat16* dst;
    float* nrm;
    if (warp < NROWS) {
        src = h + (size_t)warp * HID; dst = g_hbf + (size_t)warp * HID; nrm = &g_hsq[warp];
    } else {
        int r = warp - NROWS;
        if (r >= NCODES) return;
        src = cb + (size_t)r * HID; dst = g_cbf + (size_t)r * HID; nrm = &g_csq[r];
    }
    float s = 0.f;
#pragma unroll
    for (int half2i = 0; half2i < 2; ++half2i) {
        float4 a = ((const float4*)src)[lane + half2i * 32];
        s = fmaf(a.x, a.x, s); s = fmaf(a.y, a.y, s);
        s = fmaf(a.z, a.z, s); s = fmaf(a.w, a.w, s);
        __nv_bfloat162 p0 = __floats2bfloat162_rn(a.x, a.y);
        __nv_bfloat162 p1 = __floats2bfloat162_rn(a.z, a.w);
        uint2 w;
        w.x = *reinterpret_cast<uint32_t*>(&p0);
        w.y = *reinterpret_cast<uint32_t*>(&p1);
        ((uint2*)dst)[lane + half2i * 32] = w;
    }
#pragma unroll
    for (int o = 16; o; o >>= 1) s += __shfl_xor_sync(0xFFFFFFFFu, s, o);
    if (lane == 0) *nrm = s;
}

// ---------------------------------------------------------------------------
// bf16 HMMA GEMM: 128x128 tile per CTA (4096 CTAs), OCCUPANCY 2.
// K chunked 4x64, double-buffered cp.async.
// Epilogue: bf16 score staging -> coalesced writes + per-row tile-min index.
// ---------------------------------------------------------------------------
#define CH_STRIDE 144                    // 128B data + 16B pad, conflict-free
#define CH_MAT   (128 * CH_STRIDE)       // 18432 per matrix per chunk
#define CH_BUF   (2 * CH_MAT)            // A+B per chunk
#define SM_TOTAL (2 * CH_BUF)            // 73728 -> 2 CTAs/SM
#define SC_STRIDE 272                    // score staging row stride (bytes)
#define SM_ROWMIN 36864                  // rowmin array offset (after staging)

__global__ __launch_bounds__(256, 2) void vq_gemm_kernel() {
    extern __shared__ char smem[];
    const uint32_t sb = smem_u32(smem);
    const int tid = threadIdx.x;
    const int lane = tid & 31;
    const int wid = tid >> 5;
    const int wm = wid & 1;          // warp row (2 x 64)
    const int wn = wid >> 1;         // warp col (4 x 32)
    const int row0 = blockIdx.y * 128;
    const int col0 = blockIdx.x * 128;
    unsigned* rowmin = (unsigned*)(smem + SM_ROWMIN);

    const char* asrc = (const char*)(g_hbf + (size_t)row0 * HID);
    const char* bsrc = (const char*)(g_cbf + (size_t)col0 * HID);

    const int lr = tid >> 3;
    const int lc = tid & 7;
    auto load_chunk = [&](int ck, int buf) {
        const uint32_t bA = sb + buf * CH_BUF;
        const uint32_t bB = bA + CH_MAT;
        const int goff = ck * 128 + lc * 16;
#pragma unroll
        for (int i = 0; i < 4; ++i) {
            int r = lr + i * 32;
            cp16(bA + r * CH_STRIDE + lc * 16, asrc + r * 512 + goff);
            cp16(bB + r * CH_STRIDE + lc * 16, bsrc + r * 512 + goff);
        }
    };

    load_chunk(0, 0); CP_COMMIT();
    load_chunk(1, 1); CP_COMMIT();

    float acc[4][4][4];
#pragma unroll
    for (int mi = 0; mi < 4; ++mi)
#pragma unroll
        for (int ni = 0; ni < 4; ++ni)
#pragma unroll
            for (int q = 0; q < 4; ++q) acc[mi][ni][q] = 0.f;

    const int lrow = lane & 15;
    const int lkc  = lane >> 4;

#pragma unroll
    for (int ck = 0; ck < 4; ++ck) {
        if (ck < 3) CP_WAIT1(); else CP_WAIT0();
        __syncthreads();

        const uint32_t bufb = sb + (ck & 1) * CH_BUF;
        const uint32_t aAddr0 = bufb + (wm * 64 + lrow) * CH_STRIDE + lkc * 16;
        const uint32_t bAddr0 = bufb + CH_MAT + (wn * 32 + lrow) * CH_STRIDE + lkc * 16;
#pragma unroll
        for (int ks = 0; ks < 4; ++ks) {
            const uint32_t koff = (uint32_t)ks * 32;
            uint32_t a[4][4], b[2][4];
#pragma unroll
            for (int mi = 0; mi < 4; ++mi)
                LDSM_X4(a[mi][0], a[mi][1], a[mi][2], a[mi][3],
                        aAddr0 + mi * 16 * CH_STRIDE + koff);
#pragma unroll
            for (int nj = 0; nj < 2; ++nj)
                LDSM_X4(b[nj][0], b[nj][1], b[nj][2], b[nj][3],
                        bAddr0 + nj * 16 * CH_STRIDE + koff);
#pragma unroll
            for (int mi = 0; mi < 4; ++mi) {
#pragma unroll
                for (int nj = 0; nj < 2; ++nj) {
                    MMA16816(acc[mi][2 * nj],     a[mi][0], a[mi][1], a[mi][2], a[mi][3],
                             b[nj][0], b[nj][2]);
                    MMA16816(acc[mi][2 * nj + 1], a[mi][0], a[mi][1], a[mi][2], a[mi][3],
                             b[nj][1], b[nj][3]);
                }
            }
        }

        if (ck < 2) {
            __syncthreads();
            load_chunk(ck + 2, ck & 1);
            CP_COMMIT();
        }
    }
    __syncthreads();  // done with chunk buffers — reuse smem for staging/rowmin
    if (tid < 128) rowmin[tid] = 0xFFFFFFFFu;
    __syncthreads();

    // --- Epilogue: score = csq - 2*dot (in place) ---
    float2 csq2[4];
#pragma unroll
    for (int ni = 0; ni < 4; ++ni)
        csq2[ni] = *(const float2*)&g_csq[col0 + wn * 32 + ni * 8 + 2 * (lane & 3)];
#pragma unroll
    for (int mi = 0; mi < 4; ++mi)
#pragma unroll
        for (int ni = 0; ni < 4; ++ni) {
            acc[mi][ni][0] = csq2[ni].x - 2.0f * acc[mi][ni][0];
            acc[mi][ni][1] = csq2[ni].y - 2.0f * acc[mi][ni][1];
            acc[mi][ni][2] = csq2[ni].x - 2.0f * acc[mi][ni][2];
            acc[mi][ni][3] = csq2[ni].y - 2.0f * acc[mi][ni][3];
        }

    // per-row min across warp's 32 cols (quad shuffle) -> smem atomicMin
#pragma unroll
    for (int mi = 0; mi < 4; ++mi)
#pragma unroll
        for (int hh = 0; hh < 2; ++hh) {
            float m = acc[mi][0][2 * hh];
#pragma unroll
            for (int ni = 0; ni < 4; ++ni) {
                m = fminf(m, acc[mi][ni][2 * hh]);
                m = fminf(m, acc[mi][ni][2 * hh + 1]);
            }
            m = fminf(m, __shfl_xor_sync(0xFFFFFFFFu, m, 1));
            m = fminf(m, __shfl_xor_sync(0xFFFFFFFFu, m, 2));
            if ((lane & 3) == 0)
                atomicMin(&rowmin[wm * 64 + mi * 16 + (lane >> 2) + hh * 8], enc_f(m));
        }

    // --- stage bf16 scores in smem ---
    const int erow = wm * 64 + (lane >> 2);
    const int ecol = wn * 32 + 2 * (lane & 3);
#pragma unroll
    for (int mi = 0; mi < 4; ++mi) {
#pragma unroll
        for (int ni = 0; ni < 4; ++ni) {
            __nv_bfloat162 p01 = __floats2bfloat162_rn(acc[mi][ni][0], acc[mi][ni][1]);
            __nv_bfloat162 p23 = __floats2bfloat162_rn(acc[mi][ni][2], acc[mi][ni][3]);
            int r = erow + mi * 16;
            int cbyte = (ecol + ni * 8) * 2;
            *(uint32_t*)(smem + r * SC_STRIDE + cbyte) =
                *reinterpret_cast<uint32_t*>(&p01);
            *(uint32_t*)(smem + (r + 8) * SC_STRIDE + cbyte) =
                *reinterpret_cast<uint32_t*>(&p23);
        }
    }
    __syncthreads();

    // --- Coalesced copy-out: 128 rows x 256B + tile-min index ---
#pragma unroll
    for (int i = 0; i < 8; ++i) {
        int idx = tid + i * 256;
        int r = idx >> 4, q = idx & 15;
        uint4 v = *(const uint4*)(smem + r * SC_STRIDE + q * 16);
        *(uint4*)(g_score + (size_t)(row0 + r) * NCODES + col0 + q * 8) = v;
    }
    if (tid < 128)
        g_tmin[blockIdx.x * NROWS + row0 + tid] = dec_f(rowmin[tid]);
}

// ---------------------------------------------------------------------------
// Select: one block per row. Tile-min index -> qualifying tiles only ->
// candidates -> exact fp32 rescore -> single one-hot store + loss.
// (Output was pre-zeroed by zero_out_kernel on the forked stream.)
// ---------------------------------------------------------------------------
__global__ __launch_bounds__(256) void select_kernel(const float* __restrict__ h,
                                                     const float* __restrict__ cbp,
                                                     float* __restrict__ out) {
    const int row = blockIdx.x;
    const int tid = threadIdx.x;
    const int wid = tid >> 5;
    const int lane = tid & 31;
    const unsigned FULL = 0xFFFFFFFFu;

    __shared__ float sh[HID];
    __shared__ float stmin[NTILE];
    __shared__ float sthr;
    __shared__ int scand[MAXC];
    __shared__ int scnt;
    __shared__ unsigned long long skey;
    __shared__ unsigned sidx;

    if (tid == 0) { scnt = 0; skey = 0xFFFFFFFFFFFFFFFFull; }
    sh[tid] = h[(size_t)row * HID + tid];
    if (tid < NTILE) stmin[tid] = g_tmin[tid * NROWS + row];
    __syncthreads();

    if (wid == 0) {
        float m = fminf(stmin[lane], stmin[lane + 32]);
#pragma unroll
        for (int o = 16; o; o >>= 1) m = fminf(m, __shfl_xor_sync(FULL, m, o));
        if (lane == 0) sthr = m + EPS;
    }
    __syncthreads();
    const float thr = sthr;

    // scan only qualifying tiles (expected ~1-2)
    for (int t = wid; t < NTILE; t += 8) {
        if (stmin[t] < thr) {
            const __nv_bfloat162* sp =
                (const __nv_bfloat162*)(g_score + (size_t)row * NCODES + t * 128);
#pragma unroll
            for (int q = 0; q < 2; ++q) {
                float2 f = __bfloat1622float2(sp[lane * 2 + q]);
                if (f.x < thr) { int p = atomicAdd(&scnt, 1); if (p < MAXC) scand[p] = t * 128 + lane * 4 + q * 2; }
                if (f.y < thr) { int p = atomicAdd(&scnt, 1); if (p < MAXC) scand[p] = t * 128 + lane * 4 + q * 2 + 1; }
            }
        }
    }
    __syncthreads();

    const float hsq = g_hsq[row];
    const int nc = min(scnt, MAXC);
    for (int ci = wid; ci < nc; ci += 8) {
        int c = scand[ci];
        const float* cp = cbp + (size_t)c * HID;
        float dot = 0.f;
#pragma unroll
        for (int k = lane; k < HID; k += 32) dot = fmaf(sh[k], cp[k], dot);
#pragma unroll
        for (int o = 16; o; o >>= 1) dot += __shfl_xor_sync(FULL, dot, o);
        if (lane == 0) {
            float s = __fadd_rn(__fsub_rn(hsq, __fmul_rn(2.0f, dot)), g_csq[c]);
            atomicMin(&skey, ((u64)enc_f(s) << 32) | (unsigned)c);
        }
    }
    __syncthreads();
    if (tid == 0) sidx = (unsigned)(skey & 0xFFFFFFFFull);
    __syncthreads();
    const unsigned idx = sidx;

    // --- One-hot: single store (rest pre-zeroed on forked stream) ---
    if (tid == 0) out[(size_t)row * NCODES + idx] = 1.0f;

    // --- Loss (warp 0): exact mean((h - z_q)^2) * 1.25 ---
    if (wid == 0) {
        const float* cp = cbp + (size_t)idx * HID;
        float s = 0.f;
#pragma unroll
        for (int k = lane; k < HID; k += 32) {
            float d = sh[k] - cp[k];
            s = fmaf(d, d, s);
        }
#pragma unroll
        for (int o = 16; o; o >>= 1) s += __shfl_xor_sync(FULL, s, o);
        if (lane == 0) {
            float m = s * (1.0f / (float)HID);
            out[(size_t)NROWS * NCODES + row] = __fadd_rn(m, __fmul_rn(0.25f, m));
        }
    }
}

// ---------------------------------------------------------------------------
extern "C" void kernel_launch(void* const* d_in, const int* in_sizes, int n_in,
                              void* d_out, int out_size) {
    const float* h  = (const float*)d_in[0];   // (8192, 256)
    const float* cb = (const float*)d_in[2];   // (8192, 256)
    float* out = (float*)d_out;

    static cudaStream_t s2;
    static cudaEvent_t evFork, evJoin;
    static bool init_done = false;
    if (!init_done) {
        cudaFuncSetAttribute(vq_gemm_kernel,
                             cudaFuncAttributeMaxDynamicSharedMemorySize, SM_TOTAL);
        cudaStreamCreateWithFlags(&s2, cudaStreamNonBlocking);
        cudaEventCreateWithFlags(&evFork, cudaEventDisableTiming);
        cudaEventCreateWithFlags(&evJoin, cudaEventDisableTiming);
        init_done = true;
    }

    // Fork: zero the one-hot region on s2, concurrent with convert + GEMM.
    cudaEventRecord(evFork, 0);
    cudaStreamWaitEvent(s2, evFork, 0);
    zero_out_kernel<<<4096, 256, 0, s2>>>(out);
    cudaEventRecord(evJoin, s2);

    convert_norms_kernel<<<(NROWS + NCODES) / 8, 256>>>(h, cb);

    dim3 grid(NCODES / 128, NROWS / 128);  // (64, 64)
    vq_gemm_kernel<<<grid, 256, SM_TOTAL>>>();

    // Join: select writes into the zeroed output.
    cudaStreamWaitEvent(0, evJoin, 0);
    select_kernel<<<NROWS, 256>>>(h, cb, out);
}

// round 14
// speedup vs baseline: 1.0619x; 1.0619x over previous
#include <cuda_runtime.h>
#include <cuda_bf16.h>
#include <cstdint>

#define NROWS 8192
#define NCODES 8192
#define HID 256
#define EPS 1.0f
#define MAXC 256
#define NTILE 64                      // NCODES / 128

typedef unsigned long long u64;

// ---------------------------------------------------------------------------
// Device scratch (static globals — allocation-free)
// ---------------------------------------------------------------------------
__device__ __align__(16) __nv_bfloat16 g_hbf[NROWS * HID];
__device__ __align__(16) __nv_bfloat16 g_cbf[NCODES * HID];
__device__ float g_hsq[NROWS];
__device__ float g_csq[NCODES];
__device__ __align__(16) __nv_bfloat16 g_score[(size_t)NROWS * NCODES];  // 128 MB
__device__ __align__(16) float g_tmin[(size_t)NROWS * NTILE];            // 2 MB, [row][tile]

__device__ __forceinline__ uint32_t smem_u32(const void* p) {
    uint32_t a;
    asm("{ .reg .u64 t; cvta.to.shared.u64 t, %1; cvt.u32.u64 %0, t; }"
        : "=r"(a) : "l"(p));
    return a;
}
__device__ __forceinline__ void cp16(uint32_t dst, const void* src) {
    asm volatile("cp.async.cg.shared.global [%0], [%1], 16;" :: "r"(dst), "l"(src));
}
#define CP_COMMIT() asm volatile("cp.async.commit_group;" ::: "memory")
#define CP_WAIT0()  asm volatile("cp.async.wait_group 0;"  ::: "memory")
#define CP_WAIT1()  asm volatile("cp.async.wait_group 1;"  ::: "memory")

#define LDSM_X4(r0, r1, r2, r3, addr)                                          \
    asm volatile("ldmatrix.sync.aligned.m8n8.x4.shared.b16 {%0,%1,%2,%3}, [%4];" \
                 : "=r"(r0), "=r"(r1), "=r"(r2), "=r"(r3) : "r"(addr))

#define MMA16816(d, a0, a1, a2, a3, b0, b1)                                    \
    asm volatile(                                                              \
        "mma.sync.aligned.m16n8k16.row.col.f32.bf16.bf16.f32 "                 \
        "{%0,%1,%2,%3}, {%4,%5,%6,%7}, {%8,%9}, {%0,%1,%2,%3};"                \
        : "+f"((d)[0]), "+f"((d)[1]), "+f"((d)[2]), "+f"((d)[3])               \
        : "r"(a0), "r"(a1), "r"(a2), "r"(a3), "r"(b0), "r"(b1))

// order-preserving float<->uint map
__device__ __forceinline__ unsigned enc_f(float f) {
    unsigned u = __float_as_uint(f);
    return (u & 0x80000000u) ? ~u : (u | 0x80000000u);
}
__device__ __forceinline__ float dec_f(unsigned e) {
    unsigned u = (e & 0x80000000u) ? (e ^ 0x80000000u) : ~e;
    return __uint_as_float(u);
}

// ---------------------------------------------------------------------------
// Fused fp32->bf16 convert + squared norms (one warp per row)
// ---------------------------------------------------------------------------
__global__ void convert_norms_kernel(const float* __restrict__ h,
                                     const float* __restrict__ cb) {
    int warp = (blockIdx.x * blockDim.x + threadIdx.x) >> 5;
    int lane = threadIdx.x & 31;
    const float* src;
    __nv_bfloat16* dst;
    float* nrm;
    if (warp < NROWS) {
        src = h + (size_t)warp * HID; dst = g_hbf + (size_t)warp * HID; nrm = &g_hsq[warp];
    } else {
        int r = warp - NROWS;
        if (r >= NCODES) return;
        src = cb + (size_t)r * HID; dst = g_cbf + (size_t)r * HID; nrm = &g_csq[r];
    }
    float s = 0.f;
#pragma unroll
    for (int half2i = 0; half2i < 2; ++half2i) {
        float4 a = ((const float4*)src)[lane + half2i * 32];
        s = fmaf(a.x, a.x, s); s = fmaf(a.y, a.y, s);
        s = fmaf(a.z, a.z, s); s = fmaf(a.w, a.w, s);
        __nv_bfloat162 p0 = __floats2bfloat162_rn(a.x, a.y);
        __nv_bfloat162 p1 = __floats2bfloat162_rn(a.z, a.w);
        uint2 w;
        w.x = *reinterpret_cast<uint32_t*>(&p0);
        w.y = *reinterpret_cast<uint32_t*>(&p1);
        ((uint2*)dst)[lane + half2i * 32] = w;
    }
#pragma unroll
    for (int o = 16; o; o >>= 1) s += __shfl_xor_sync(0xFFFFFFFFu, s, o);
    if (lane == 0) *nrm = s;
}

// ---------------------------------------------------------------------------
// bf16 HMMA GEMM: 128x128 tile per CTA (4096 CTAs), OCCUPANCY 2.
// K chunked 4x64, double-buffered cp.async.
// Epilogue: bf16 score staging -> coalesced writes + per-row tile-min index.
// ---------------------------------------------------------------------------
#define CH_STRIDE 144                    // 128B data + 16B pad, conflict-free
#define CH_MAT   (128 * CH_STRIDE)       // 18432 per matrix per chunk
#define CH_BUF   (2 * CH_MAT)            // A+B per chunk
#define SM_TOTAL (2 * CH_BUF)            // 73728 -> 2 CTAs/SM
#define SC_STRIDE 272                    // score staging row stride (bytes)
#define SM_ROWMIN 36864                  // rowmin array offset (after staging)

__global__ __launch_bounds__(256, 2) void vq_gemm_kernel() {
    extern __shared__ char smem[];
    const uint32_t sb = smem_u32(smem);
    const int tid = threadIdx.x;
    const int lane = tid & 31;
    const int wid = tid >> 5;
    const int wm = wid & 1;          // warp row (2 x 64)
    const int wn = wid >> 1;         // warp col (4 x 32)
    const int row0 = blockIdx.y * 128;
    const int col0 = blockIdx.x * 128;
    unsigned* rowmin = (unsigned*)(smem + SM_ROWMIN);

    const char* asrc = (const char*)(g_hbf + (size_t)row0 * HID);
    const char* bsrc = (const char*)(g_cbf + (size_t)col0 * HID);

    const int lr = tid >> 3;
    const int lc = tid & 7;
    auto load_chunk = [&](int ck, int buf) {
        const uint32_t bA = sb + buf * CH_BUF;
        const uint32_t bB = bA + CH_MAT;
        const int goff = ck * 128 + lc * 16;
#pragma unroll
        for (int i = 0; i < 4; ++i) {
            int r = lr + i * 32;
            cp16(bA + r * CH_STRIDE + lc * 16, asrc + r * 512 + goff);
            cp16(bB + r * CH_STRIDE + lc * 16, bsrc + r * 512 + goff);
        }
    };

    load_chunk(0, 0); CP_COMMIT();
    load_chunk(1, 1); CP_COMMIT();

    float acc[4][4][4];
#pragma unroll
    for (int mi = 0; mi < 4; ++mi)
#pragma unroll
        for (int ni = 0; ni < 4; ++ni)
#pragma unroll
            for (int q = 0; q < 4; ++q) acc[mi][ni][q] = 0.f;

    const int lrow = lane & 15;
    const int lkc  = lane >> 4;

#pragma unroll
    for (int ck = 0; ck < 4; ++ck) {
        if (ck < 3) CP_WAIT1(); else CP_WAIT0();
        __syncthreads();

        const uint32_t bufb = sb + (ck & 1) * CH_BUF;
        const uint32_t aAddr0 = bufb + (wm * 64 + lrow) * CH_STRIDE + lkc * 16;
        const uint32_t bAddr0 = bufb + CH_MAT + (wn * 32 + lrow) * CH_STRIDE + lkc * 16;
#pragma unroll
        for (int ks = 0; ks < 4; ++ks) {
            const uint32_t koff = (uint32_t)ks * 32;
            uint32_t a[4][4], b[2][4];
#pragma unroll
            for (int mi = 0; mi < 4; ++mi)
                LDSM_X4(a[mi][0], a[mi][1], a[mi][2], a[mi][3],
                        aAddr0 + mi * 16 * CH_STRIDE + koff);
#pragma unroll
            for (int nj = 0; nj < 2; ++nj)
                LDSM_X4(b[nj][0], b[nj][1], b[nj][2], b[nj][3],
                        bAddr0 + nj * 16 * CH_STRIDE + koff);
#pragma unroll
            for (int mi = 0; mi < 4; ++mi) {
#pragma unroll
                for (int nj = 0; nj < 2; ++nj) {
                    MMA16816(acc[mi][2 * nj],     a[mi][0], a[mi][1], a[mi][2], a[mi][3],
                             b[nj][0], b[nj][2]);
                    MMA16816(acc[mi][2 * nj + 1], a[mi][0], a[mi][1], a[mi][2], a[mi][3],
                             b[nj][1], b[nj][3]);
                }
            }
        }

        if (ck < 2) {
            __syncthreads();
            load_chunk(ck + 2, ck & 1);
            CP_COMMIT();
        }
    }
    __syncthreads();  // done with chunk buffers — reuse smem for staging/rowmin
    if (tid < 128) rowmin[tid] = 0xFFFFFFFFu;
    __syncthreads();

    // --- Epilogue: score = csq - 2*dot (in place) ---
    float2 csq2[4];
#pragma unroll
    for (int ni = 0; ni < 4; ++ni)
        csq2[ni] = *(const float2*)&g_csq[col0 + wn * 32 + ni * 8 + 2 * (lane & 3)];
#pragma unroll
    for (int mi = 0; mi < 4; ++mi)
#pragma unroll
        for (int ni = 0; ni < 4; ++ni) {
            acc[mi][ni][0] = csq2[ni].x - 2.0f * acc[mi][ni][0];
            acc[mi][ni][1] = csq2[ni].y - 2.0f * acc[mi][ni][1];
            acc[mi][ni][2] = csq2[ni].x - 2.0f * acc[mi][ni][2];
            acc[mi][ni][3] = csq2[ni].y - 2.0f * acc[mi][ni][3];
        }

    // per-row min across warp's 32 cols (quad shuffle) -> smem atomicMin
#pragma unroll
    for (int mi = 0; mi < 4; ++mi)
#pragma unroll
        for (int hh = 0; hh < 2; ++hh) {
            float m = acc[mi][0][2 * hh];
#pragma unroll
            for (int ni = 0; ni < 4; ++ni) {
                m = fminf(m, acc[mi][ni][2 * hh]);
                m = fminf(m, acc[mi][ni][2 * hh + 1]);
            }
            m = fminf(m, __shfl_xor_sync(0xFFFFFFFFu, m, 1));
            m = fminf(m, __shfl_xor_sync(0xFFFFFFFFu, m, 2));
            if ((lane & 3) == 0)
                atomicMin(&rowmin[wm * 64 + mi * 16 + (lane >> 2) + hh * 8], enc_f(m));
        }

    // --- stage bf16 scores in smem ---
    const int erow = wm * 64 + (lane >> 2);
    const int ecol = wn * 32 + 2 * (lane & 3);
#pragma unroll
    for (int mi = 0; mi < 4; ++mi) {
#pragma unroll
        for (int ni = 0; ni < 4; ++ni) {
            __nv_bfloat162 p01 = __floats2bfloat162_rn(acc[mi][ni][0], acc[mi][ni][1]);
            __nv_bfloat162 p23 = __floats2bfloat162_rn(acc[mi][ni][2], acc[mi][ni][3]);
            int r = erow + mi * 16;
            int cbyte = (ecol + ni * 8) * 2;
            *(uint32_t*)(smem + r * SC_STRIDE + cbyte) =
                *reinterpret_cast<uint32_t*>(&p01);
            *(uint32_t*)(smem + (r + 8) * SC_STRIDE + cbyte) =
                *reinterpret_cast<uint32_t*>(&p23);
        }
    }
    __syncthreads();

    // --- Coalesced copy-out: 128 rows x 256B + tile-min index ([row][tile]) ---
#pragma unroll
    for (int i = 0; i < 8; ++i) {
        int idx = tid + i * 256;
        int r = idx >> 4, q = idx & 15;
        uint4 v = *(const uint4*)(smem + r * SC_STRIDE + q * 16);
        *(uint4*)(g_score + (size_t)(row0 + r) * NCODES + col0 + q * 8) = v;
    }
    if (tid < 128)
        g_tmin[(size_t)(row0 + tid) * NTILE + blockIdx.x] = dec_f(rowmin[tid]);
}

// ---------------------------------------------------------------------------
// Select + output: one block per row.
// (1) fire the full zero stream for this row (no dependencies),
// (2) tile-min scan -> qualifying tiles -> candidates -> exact fp32 rescore,
// (3) __syncthreads (orders the zero stores block-wide), (4) hot store + loss.
// ---------------------------------------------------------------------------
__global__ __launch_bounds__(256) void select_kernel(const float* __restrict__ h,
                                                     const float* __restrict__ cbp,
                                                     float* __restrict__ out) {
    const int row = blockIdx.x;
    const int tid = threadIdx.x;
    const int wid = tid >> 5;
    const int lane = tid & 31;
    const unsigned FULL = 0xFFFFFFFFu;

    __shared__ float sh[HID];
    __shared__ float stmin[NTILE];
    __shared__ float sthr;
    __shared__ int scand[MAXC];
    __shared__ int scnt;
    __shared__ unsigned long long skey;
    __shared__ unsigned sidx;

    // --- (1) zero stream: 2048 x 16B = full row, independent of everything ---
    uint4* orow = (uint4*)(out + (size_t)row * NCODES);
    const uint4 z = make_uint4(0, 0, 0, 0);
#pragma unroll
    for (int it = 0; it < 8; ++it) orow[it * 256 + tid] = z;

    // --- (2) selection logic (overlaps with store drain) ---
    if (tid == 0) { scnt = 0; skey = 0xFFFFFFFFFFFFFFFFull; }
    sh[tid] = h[(size_t)row * HID + tid];
    if (tid < NTILE) stmin[tid] = g_tmin[(size_t)row * NTILE + tid];  // coalesced
    __syncthreads();

    if (wid == 0) {
        float m = fminf(stmin[lane], stmin[lane + 32]);
#pragma unroll
        for (int o = 16; o; o >>= 1) m = fminf(m, __shfl_xor_sync(FULL, m, o));
        if (lane == 0) sthr = m + EPS;
    }
    __syncthreads();
    const float thr = sthr;

    // scan only qualifying tiles (expected ~1-2)
    for (int t = wid; t < NTILE; t += 8) {
        if (stmin[t] < thr) {
            const __nv_bfloat162* sp =
                (const __nv_bfloat162*)(g_score + (size_t)row * NCODES + t * 128);
#pragma unroll
            for (int q = 0; q < 2; ++q) {
                float2 f = __bfloat1622float2(sp[lane * 2 + q]);
                if (f.x < thr) { int p = atomicAdd(&scnt, 1); if (p < MAXC) scand[p] = t * 128 + lane * 4 + q * 2; }
                if (f.y < thr) { int p = atomicAdd(&scnt, 1); if (p < MAXC) scand[p] = t * 128 + lane * 4 + q * 2 + 1; }
            }
        }
    }
    __syncthreads();

    const float hsq = g_hsq[row];
    const int nc = min(scnt, MAXC);
    for (int ci = wid; ci < nc; ci += 8) {
        int c = scand[ci];
        const float* cp = cbp + (size_t)c * HID;
        float dot = 0.f;
#pragma unroll
        for (int k = lane; k < HID; k += 32) dot = fmaf(sh[k], cp[k], dot);
#pragma unroll
        for (int o = 16; o; o >>= 1) dot += __shfl_xor_sync(FULL, dot, o);
        if (lane == 0) {
            float s = __fadd_rn(__fsub_rn(hsq, __fmul_rn(2.0f, dot)), g_csq[c]);
            atomicMin(&skey, ((u64)enc_f(s) << 32) | (unsigned)c);
        }
    }
    __syncthreads();
    if (tid == 0) sidx = (unsigned)(skey & 0xFFFFFFFFull);

    // --- (3) order the zero stores, then (4) hot store + loss ---
    __syncthreads();
    const unsigned idx = sidx;
    if (tid == 0) out[(size_t)row * NCODES + idx] = 1.0f;

    if (wid == 0) {
        const float* cp = cbp + (size_t)idx * HID;
        float s = 0.f;
#pragma unroll
        for (int k = lane; k < HID; k += 32) {
            float d = sh[k] - cp[k];
            s = fmaf(d, d, s);
        }
#pragma unroll
        for (int o = 16; o; o >>= 1) s += __shfl_xor_sync(FULL, s, o);
        if (lane == 0) {
            float m = s * (1.0f / (float)HID);
            out[(size_t)NROWS * NCODES + row] = __fadd_rn(m, __fmul_rn(0.25f, m));
        }
    }
}

// ---------------------------------------------------------------------------
extern "C" void kernel_launch(void* const* d_in, const int* in_sizes, int n_in,
                              void* d_out, int out_size) {
    const float* h  = (const float*)d_in[0];   // (8192, 256)
    const float* cb = (const float*)d_in[2];   // (8192, 256)
    float* out = (float*)d_out;

    static bool attr_set = false;
    if (!attr_set) {
        cudaFuncSetAttribute(vq_gemm_kernel,
                             cudaFuncAttributeMaxDynamicSharedMemorySize, SM_TOTAL);
        attr_set = true;
    }

    convert_norms_kernel<<<(NROWS + NCODES) / 8, 256>>>(h, cb);

    dim3 grid(NCODES / 128, NROWS / 128);  // (64, 64)
    vq_gemm_kernel<<<grid, 256, SM_TOTAL>>>();

    select_kernel<<<NROWS, 256>>>(h, cb, out);
}

// round 15
// speedup vs baseline: 1.0847x; 1.0214x over previous
#include <cuda_runtime.h>
#include <cuda_bf16.h>
#include <cstdint>

#define NROWS 8192
#define NCODES 8192
#define HID 256
#define EPS 1.0f
#define MAXC 256
#define NTILE 64                      // NCODES / 128
#define ZROWS 2048                    // rows pre-zeroed by convert kernel

typedef unsigned long long u64;

// ---------------------------------------------------------------------------
// Device scratch (static globals — allocation-free)
// ---------------------------------------------------------------------------
__device__ __align__(16) __nv_bfloat16 g_hbf[NROWS * HID];
__device__ __align__(16) __nv_bfloat16 g_cbf[NCODES * HID];
__device__ float g_hsq[NROWS];
__device__ float g_csq[NCODES];
__device__ __align__(16) __nv_bfloat16 g_score[(size_t)NROWS * NCODES];  // 128 MB
__device__ __align__(16) float g_tmin[(size_t)NROWS * NTILE];            // 2 MB, [row][tile]

__device__ __forceinline__ uint32_t smem_u32(const void* p) {
    uint32_t a;
    asm("{ .reg .u64 t; cvta.to.shared.u64 t, %1; cvt.u32.u64 %0, t; }"
        : "=r"(a) : "l"(p));
    return a;
}
__device__ __forceinline__ void cp16(uint32_t dst, const void* src) {
    asm volatile("cp.async.cg.shared.global [%0], [%1], 16;" :: "r"(dst), "l"(src));
}
#define CP_COMMIT() asm volatile("cp.async.commit_group;" ::: "memory")
#define CP_WAIT0()  asm volatile("cp.async.wait_group 0;"  ::: "memory")
#define CP_WAIT1()  asm volatile("cp.async.wait_group 1;"  ::: "memory")

// streaming store (evict-first): 16B of zeros / data
__device__ __forceinline__ void st16_cs(void* p, uint4 v) {
    asm volatile("st.global.cs.v4.u32 [%0], {%1,%2,%3,%4};"
                 :: "l"(p), "r"(v.x), "r"(v.y), "r"(v.z), "r"(v.w) : "memory");
}

#define LDSM_X4(r0, r1, r2, r3, addr)                                          \
    asm volatile("ldmatrix.sync.aligned.m8n8.x4.shared.b16 {%0,%1,%2,%3}, [%4];" \
                 : "=r"(r0), "=r"(r1), "=r"(r2), "=r"(r3) : "r"(addr))

#define MMA16816(d, a0, a1, a2, a3, b0, b1)                                    \
    asm volatile(                                                              \
        "mma.sync.aligned.m16n8k16.row.col.f32.bf16.bf16.f32 "                 \
        "{%0,%1,%2,%3}, {%4,%5,%6,%7}, {%8,%9}, {%0,%1,%2,%3};"                \
        : "+f"((d)[0]), "+f"((d)[1]), "+f"((d)[2]), "+f"((d)[3])               \
        : "r"(a0), "r"(a1), "r"(a2), "r"(a3), "r"(b0), "r"(b1))

// order-preserving float<->uint map
__device__ __forceinline__ unsigned enc_f(float f) {
    unsigned u = __float_as_uint(f);
    return (u & 0x80000000u) ? ~u : (u | 0x80000000u);
}
__device__ __forceinline__ float dec_f(unsigned e) {
    unsigned u = (e & 0x80000000u) ? (e ^ 0x80000000u) : ~e;
    return __uint_as_float(u);
}

// ---------------------------------------------------------------------------
// Fused fp32->bf16 convert + squared norms (one warp per row)
// + pre-zero of output rows [0, ZROWS) (one block per row, idle store BW)
// ---------------------------------------------------------------------------
__global__ void convert_norms_kernel(const float* __restrict__ h,
                                     const float* __restrict__ cb,
                                     float* __restrict__ out) {
    int warp = (blockIdx.x * blockDim.x + threadIdx.x) >> 5;
    int lane = threadIdx.x & 31;
    const float* src;
    __nv_bfloat16* dst;
    float* nrm;
    if (warp < NROWS) {
        src = h + (size_t)warp * HID; dst = g_hbf + (size_t)warp * HID; nrm = &g_hsq[warp];
    } else {
        src = cb + (size_t)(warp - NROWS) * HID;
        dst = g_cbf + (size_t)(warp - NROWS) * HID;
        nrm = &g_csq[warp - NROWS];
    }
    float s = 0.f;
#pragma unroll
    for (int half2i = 0; half2i < 2; ++half2i) {
        float4 a = ((const float4*)src)[lane + half2i * 32];
        s = fmaf(a.x, a.x, s); s = fmaf(a.y, a.y, s);
        s = fmaf(a.z, a.z, s); s = fmaf(a.w, a.w, s);
        __nv_bfloat162 p0 = __floats2bfloat162_rn(a.x, a.y);
        __nv_bfloat162 p1 = __floats2bfloat162_rn(a.z, a.w);
        uint2 w;
        w.x = *reinterpret_cast<uint32_t*>(&p0);
        w.y = *reinterpret_cast<uint32_t*>(&p1);
        ((uint2*)dst)[lane + half2i * 32] = w;
    }
#pragma unroll
    for (int o = 16; o; o >>= 1) s += __shfl_xor_sync(0xFFFFFFFFu, s, o);
    if (lane == 0) *nrm = s;

    // --- pre-zero one output row per block (rows [0, ZROWS)) ---
    if (blockIdx.x < ZROWS) {
        uint4* orow = (uint4*)(out + (size_t)blockIdx.x * NCODES);
        const uint4 z = make_uint4(0, 0, 0, 0);
#pragma unroll
        for (int it = 0; it < 8; ++it)
            st16_cs(&orow[it * 256 + threadIdx.x], z);
    }
}

// ---------------------------------------------------------------------------
// bf16 HMMA GEMM: 128x128 tile per CTA (4096 CTAs), OCCUPANCY 2.
// K chunked 4x64, double-buffered cp.async.
// Epilogue: bf16 score staging -> coalesced writes + per-row tile-min index.
// ---------------------------------------------------------------------------
#define CH_STRIDE 144                    // 128B data + 16B pad, conflict-free
#define CH_MAT   (128 * CH_STRIDE)       // 18432 per matrix per chunk
#define CH_BUF   (2 * CH_MAT)            // A+B per chunk
#define SM_TOTAL (2 * CH_BUF)            // 73728 -> 2 CTAs/SM
#define SC_STRIDE 272                    // score staging row stride (bytes)
#define SM_ROWMIN 36864                  // rowmin array offset (after staging)

__global__ __launch_bounds__(256, 2) void vq_gemm_kernel() {
    extern __shared__ char smem[];
    const uint32_t sb = smem_u32(smem);
    const int tid = threadIdx.x;
    const int lane = tid & 31;
    const int wid = tid >> 5;
    const int wm = wid & 1;          // warp row (2 x 64)
    const int wn = wid >> 1;         // warp col (4 x 32)
    const int row0 = blockIdx.y * 128;
    const int col0 = blockIdx.x * 128;
    unsigned* rowmin = (unsigned*)(smem + SM_ROWMIN);

    const char* asrc = (const char*)(g_hbf + (size_t)row0 * HID);
    const char* bsrc = (const char*)(g_cbf + (size_t)col0 * HID);

    const int lr = tid >> 3;
    const int lc = tid & 7;
    auto load_chunk = [&](int ck, int buf) {
        const uint32_t bA = sb + buf * CH_BUF;
        const uint32_t bB = bA + CH_MAT;
        const int goff = ck * 128 + lc * 16;
#pragma unroll
        for (int i = 0; i < 4; ++i) {
            int r = lr + i * 32;
            cp16(bA + r * CH_STRIDE + lc * 16, asrc + r * 512 + goff);
            cp16(bB + r * CH_STRIDE + lc * 16, bsrc + r * 512 + goff);
        }
    };

    load_chunk(0, 0); CP_COMMIT();
    load_chunk(1, 1); CP_COMMIT();

    float acc[4][4][4];
#pragma unroll
    for (int mi = 0; mi < 4; ++mi)
#pragma unroll
        for (int ni = 0; ni < 4; ++ni)
#pragma unroll
            for (int q = 0; q < 4; ++q) acc[mi][ni][q] = 0.f;

    const int lrow = lane & 15;
    const int lkc  = lane >> 4;

#pragma unroll
    for (int ck = 0; ck < 4; ++ck) {
        if (ck < 3) CP_WAIT1(); else CP_WAIT0();
        __syncthreads();

        const uint32_t bufb = sb + (ck & 1) * CH_BUF;
        const uint32_t aAddr0 = bufb + (wm * 64 + lrow) * CH_STRIDE + lkc * 16;
        const uint32_t bAddr0 = bufb + CH_MAT + (wn * 32 + lrow) * CH_STRIDE + lkc * 16;
#pragma unroll
        for (int ks = 0; ks < 4; ++ks) {
            const uint32_t koff = (uint32_t)ks * 32;
            uint32_t a[4][4], b[2][4];
#pragma unroll
            for (int mi = 0; mi < 4; ++mi)
                LDSM_X4(a[mi][0], a[mi][1], a[mi][2], a[mi][3],
                        aAddr0 + mi * 16 * CH_STRIDE + koff);
#pragma unroll
            for (int nj = 0; nj < 2; ++nj)
                LDSM_X4(b[nj][0], b[nj][1], b[nj][2], b[nj][3],
                        bAddr0 + nj * 16 * CH_STRIDE + koff);
#pragma unroll
            for (int mi = 0; mi < 4; ++mi) {
#pragma unroll
                for (int nj = 0; nj < 2; ++nj) {
                    MMA16816(acc[mi][2 * nj],     a[mi][0], a[mi][1], a[mi][2], a[mi][3],
                             b[nj][0], b[nj][2]);
                    MMA16816(acc[mi][2 * nj + 1], a[mi][0], a[mi][1], a[mi][2], a[mi][3],
                             b[nj][1], b[nj][3]);
                }
            }
        }

        if (ck < 2) {
            __syncthreads();
            load_chunk(ck + 2, ck & 1);
            CP_COMMIT();
        }
    }
    __syncthreads();  // done with chunk buffers — reuse smem for staging/rowmin
    if (tid < 128) rowmin[tid] = 0xFFFFFFFFu;
    __syncthreads();

    // --- Epilogue: score = csq - 2*dot (in place) ---
    float2 csq2[4];
#pragma unroll
    for (int ni = 0; ni < 4; ++ni)
        csq2[ni] = *(const float2*)&g_csq[col0 + wn * 32 + ni * 8 + 2 * (lane & 3)];
#pragma unroll
    for (int mi = 0; mi < 4; ++mi)
#pragma unroll
        for (int ni = 0; ni < 4; ++ni) {
            acc[mi][ni][0] = csq2[ni].x - 2.0f * acc[mi][ni][0];
            acc[mi][ni][1] = csq2[ni].y - 2.0f * acc[mi][ni][1];
            acc[mi][ni][2] = csq2[ni].x - 2.0f * acc[mi][ni][2];
            acc[mi][ni][3] = csq2[ni].y - 2.0f * acc[mi][ni][3];
        }

    // per-row min across warp's 32 cols (quad shuffle) -> smem atomicMin
#pragma unroll
    for (int mi = 0; mi < 4; ++mi)
#pragma unroll
        for (int hh = 0; hh < 2; ++hh) {
            float m = acc[mi][0][2 * hh];
#pragma unroll
            for (int ni = 0; ni < 4; ++ni) {
                m = fminf(m, acc[mi][ni][2 * hh]);
                m = fminf(m, acc[mi][ni][2 * hh + 1]);
            }
            m = fminf(m, __shfl_xor_sync(0xFFFFFFFFu, m, 1));
            m = fminf(m, __shfl_xor_sync(0xFFFFFFFFu, m, 2));
            if ((lane & 3) == 0)
                atomicMin(&rowmin[wm * 64 + mi * 16 + (lane >> 2) + hh * 8], enc_f(m));
        }

    // --- stage bf16 scores in smem ---
    const int erow = wm * 64 + (lane >> 2);
    const int ecol = wn * 32 + 2 * (lane & 3);
#pragma unroll
    for (int mi = 0; mi < 4; ++mi) {
#pragma unroll
        for (int ni = 0; ni < 4; ++ni) {
            __nv_bfloat162 p01 = __floats2bfloat162_rn(acc[mi][ni][0], acc[mi][ni][1]);
            __nv_bfloat162 p23 = __floats2bfloat162_rn(acc[mi][ni][2], acc[mi][ni][3]);
            int r = erow + mi * 16;
            int cbyte = (ecol + ni * 8) * 2;
            *(uint32_t*)(smem + r * SC_STRIDE + cbyte) =
                *reinterpret_cast<uint32_t*>(&p01);
            *(uint32_t*)(smem + (r + 8) * SC_STRIDE + cbyte) =
                *reinterpret_cast<uint32_t*>(&p23);
        }
    }
    __syncthreads();

    // --- Coalesced copy-out: 128 rows x 256B + tile-min index ([row][tile]) ---
#pragma unroll
    for (int i = 0; i < 8; ++i) {
        int idx = tid + i * 256;
        int r = idx >> 4, q = idx & 15;
        uint4 v = *(const uint4*)(smem + r * SC_STRIDE + q * 16);
        *(uint4*)(g_score + (size_t)(row0 + r) * NCODES + col0 + q * 8) = v;
    }
    if (tid < 128)
        g_tmin[(size_t)(row0 + tid) * NTILE + blockIdx.x] = dec_f(rowmin[tid]);
}

// ---------------------------------------------------------------------------
// Select + output: one block per row.
// (1) zero stream (rows >= ZROWS only; .cs streaming stores),
// (2) tile-min scan -> qualifying tiles -> candidates -> exact fp32 rescore,
// (3) __syncthreads (orders the zero stores block-wide), (4) hot store + loss.
// ---------------------------------------------------------------------------
__global__ __launch_bounds__(256) void select_kernel(const float* __restrict__ h,
                                                     const float* __restrict__ cbp,
                                                     float* __restrict__ out) {
    const int row = blockIdx.x;
    const int tid = threadIdx.x;
    const int wid = tid >> 5;
    const int lane = tid & 31;
    const unsigned FULL = 0xFFFFFFFFu;

    __shared__ float sh[HID];
    __shared__ float stmin[NTILE];
    __shared__ float sthr;
    __shared__ int scand[MAXC];
    __shared__ int scnt;
    __shared__ unsigned long long skey;
    __shared__ unsigned sidx;

    // --- (1) zero stream (skip rows pre-zeroed by convert) ---
    uint4* orow = (uint4*)(out + (size_t)row * NCODES);
    if (row >= ZROWS) {
        const uint4 z = make_uint4(0, 0, 0, 0);
#pragma unroll
        for (int it = 0; it < 8; ++it)
            st16_cs(&orow[it * 256 + tid], z);
    }

    // --- (2) selection logic (overlaps with store drain) ---
    if (tid == 0) { scnt = 0; skey = 0xFFFFFFFFFFFFFFFFull; }
    sh[tid] = h[(size_t)row * HID + tid];
    if (tid < NTILE) stmin[tid] = g_tmin[(size_t)row * NTILE + tid];  // coalesced
    __syncthreads();

    if (wid == 0) {
        float m = fminf(stmin[lane], stmin[lane + 32]);
#pragma unroll
        for (int o = 16; o; o >>= 1) m = fminf(m, __shfl_xor_sync(FULL, m, o));
        if (lane == 0) sthr = m + EPS;
    }
    __syncthreads();
    const float thr = sthr;

    // scan only qualifying tiles (expected ~1-2)
    for (int t = wid; t < NTILE; t += 8) {
        if (stmin[t] < thr) {
            const __nv_bfloat162* sp =
                (const __nv_bfloat162*)(g_score + (size_t)row * NCODES + t * 128);
#pragma unroll
            for (int q = 0; q < 2; ++q) {
                float2 f = __bfloat1622float2(sp[lane * 2 + q]);
                if (f.x < thr) { int p = atomicAdd(&scnt, 1); if (p < MAXC) scand[p] = t * 128 + lane * 4 + q * 2; }
                if (f.y < thr) { int p = atomicAdd(&scnt, 1); if (p < MAXC) scand[p] = t * 128 + lane * 4 + q * 2 + 1; }
            }
        }
    }
    __syncthreads();

    const float hsq = g_hsq[row];
    const int nc = min(scnt, MAXC);
    for (int ci = wid; ci < nc; ci += 8) {
        int c = scand[ci];
        const float* cp = cbp + (size_t)c * HID;
        float dot = 0.f;
#pragma unroll
        for (int k = lane; k < HID; k += 32) dot = fmaf(sh[k], cp[k], dot);
#pragma unroll
        for (int o = 16; o; o >>= 1) dot += __shfl_xor_sync(FULL, dot, o);
        if (lane == 0) {
            float s = __fadd_rn(__fsub_rn(hsq, __fmul_rn(2.0f, dot)), g_csq[c]);
            atomicMin(&skey, ((u64)enc_f(s) << 32) | (unsigned)c);
        }
    }
    __syncthreads();
    if (tid == 0) sidx = (unsigned)(skey & 0xFFFFFFFFull);

    // --- (3) order the zero stores, then (4) hot store + loss ---
    __syncthreads();
    const unsigned idx = sidx;
    if (tid == 0) out[(size_t)row * NCODES + idx] = 1.0f;

    if (wid == 0) {
        const float* cp = cbp + (size_t)idx * HID;
        float s = 0.f;
#pragma unroll
        for (int k = lane; k < HID; k += 32) {
            float d = sh[k] - cp[k];
            s = fmaf(d, d, s);
        }
#pragma unroll
        for (int o = 16; o; o >>= 1) s += __shfl_xor_sync(FULL, s, o);
        if (lane == 0) {
            float m = s * (1.0f / (float)HID);
            out[(size_t)NROWS * NCODES + row] = __fadd_rn(m, __fmul_rn(0.25f, m));
        }
    }
}

// ---------------------------------------------------------------------------
extern "C" void kernel_launch(void* const* d_in, const int* in_sizes, int n_in,
                              void* d_out, int out_size) {
    const float* h  = (const float*)d_in[0];   // (8192, 256)
    const float* cb = (const float*)d_in[2];   // (8192, 256)
    float* out = (float*)d_out;

    static bool attr_set = false;
    if (!attr_set) {
        cudaFuncSetAttribute(vq_gemm_kernel,
                             cudaFuncAttributeMaxDynamicSharedMemorySize, SM_TOTAL);
        attr_set = true;
    }

    convert_norms_kernel<<<(NROWS + NCODES) / 8, 256>>>(h, cb, out);

    dim3 grid(NCODES / 128, NROWS / 128);  // (64, 64)
    vq_gemm_kernel<<<grid, 256, SM_TOTAL>>>();

    select_kernel<<<NROWS, 256>>>(h, cb, out);
}

// round 16
// speedup vs baseline: 1.1307x; 1.0423x over previous
#include <cuda_runtime.h>
#include <cuda_bf16.h>
#include <cstdint>

#define NROWS 8192
#define NCODES 8192
#define HID 256
#define EPS 1.0f
#define MAXC 256
#define NTILE 64                      // NCODES / 128

typedef unsigned long long u64;

// ---------------------------------------------------------------------------
// Device scratch (static globals — allocation-free)
// ---------------------------------------------------------------------------
__device__ __align__(16) __nv_bfloat16 g_hbf[NROWS * HID];
__device__ __align__(16) __nv_bfloat16 g_cbf[NCODES * HID];
__device__ float g_hsq[NROWS];
__device__ float g_csq[NCODES];
__device__ __align__(16) __nv_bfloat16 g_score[(size_t)NROWS * NCODES];  // 128 MB
__device__ __align__(16) float g_tmin[(size_t)NROWS * NTILE];            // 2 MB, [row][tile]

__device__ __forceinline__ uint32_t smem_u32(const void* p) {
    uint32_t a;
    asm("{ .reg .u64 t; cvta.to.shared.u64 t, %1; cvt.u32.u64 %0, t; }"
        : "=r"(a) : "l"(p));
    return a;
}
__device__ __forceinline__ void cp16(uint32_t dst, const void* src) {
    asm volatile("cp.async.cg.shared.global [%0], [%1], 16;" :: "r"(dst), "l"(src));
}
#define CP_COMMIT() asm volatile("cp.async.commit_group;" ::: "memory")
#define CP_WAIT0()  asm volatile("cp.async.wait_group 0;"  ::: "memory")
#define CP_WAIT1()  asm volatile("cp.async.wait_group 1;"  ::: "memory")

// streaming store (evict-first): 16B
__device__ __forceinline__ void st16_cs(void* p, uint4 v) {
    asm volatile("st.global.cs.v4.u32 [%0], {%1,%2,%3,%4};"
                 :: "l"(p), "r"(v.x), "r"(v.y), "r"(v.z), "r"(v.w) : "memory");
}

#define LDSM_X4(r0, r1, r2, r3, addr)                                          \
    asm volatile("ldmatrix.sync.aligned.m8n8.x4.shared.b16 {%0,%1,%2,%3}, [%4];" \
                 : "=r"(r0), "=r"(r1), "=r"(r2), "=r"(r3) : "r"(addr))

#define MMA16816(d, a0, a1, a2, a3, b0, b1)                                    \
    asm volatile(                                                              \
        "mma.sync.aligned.m16n8k16.row.col.f32.bf16.bf16.f32 "                 \
        "{%0,%1,%2,%3}, {%4,%5,%6,%7}, {%8,%9}, {%0,%1,%2,%3};"                \
        : "+f"((d)[0]), "+f"((d)[1]), "+f"((d)[2]), "+f"((d)[3])               \
        : "r"(a0), "r"(a1), "r"(a2), "r"(a3), "r"(b0), "r"(b1))

// order-preserving float<->uint map
__device__ __forceinline__ unsigned enc_f(float f) {
    unsigned u = __float_as_uint(f);
    return (u & 0x80000000u) ? ~u : (u | 0x80000000u);
}
__device__ __forceinline__ float dec_f(unsigned e) {
    unsigned u = (e & 0x80000000u) ? (e ^ 0x80000000u) : ~e;
    return __uint_as_float(u);
}

// ---------------------------------------------------------------------------
// Fused fp32->bf16 convert + squared norms (one warp per row)
// ---------------------------------------------------------------------------
__global__ void convert_norms_kernel(const float* __restrict__ h,
                                     const float* __restrict__ cb) {
    int warp = (blockIdx.x * blockDim.x + threadIdx.x) >> 5;
    int lane = threadIdx.x & 31;
    const float* src;
    __nv_bfloat16* dst;
    float* nrm;
    if (warp < NROWS) {
        src = h + (size_t)warp * HID; dst = g_hbf + (size_t)warp * HID; nrm = &g_hsq[warp];
    } else {
        src = cb + (size_t)(warp - NROWS) * HID;
        dst = g_cbf + (size_t)(warp - NROWS) * HID;
        nrm = &g_csq[warp - NROWS];
    }
    float s = 0.f;
#pragma unroll
    for (int half2i = 0; half2i < 2; ++half2i) {
        float4 a = ((const float4*)src)[lane + half2i * 32];
        s = fmaf(a.x, a.x, s); s = fmaf(a.y, a.y, s);
        s = fmaf(a.z, a.z, s); s = fmaf(a.w, a.w, s);
        __nv_bfloat162 p0 = __floats2bfloat162_rn(a.x, a.y);
        __nv_bfloat162 p1 = __floats2bfloat162_rn(a.z, a.w);
        uint2 w;
        w.x = *reinterpret_cast<uint32_t*>(&p0);
        w.y = *reinterpret_cast<uint32_t*>(&p1);
        ((uint2*)dst)[lane + half2i * 32] = w;
    }
#pragma unroll
    for (int o = 16; o; o >>= 1) s += __shfl_xor_sync(0xFFFFFFFFu, s, o);
    if (lane == 0) *nrm = s;
}

// ---------------------------------------------------------------------------
// bf16 HMMA GEMM: 128x128 tile per CTA (4096 CTAs), OCCUPANCY 2.
// K chunked 4x64, double-buffered cp.async.
// Zeroes its own 128x128 output chunk (.cs stores issued at kernel start,
// drain under the mainloop — R7/R10 differential showed this is ~free).
// Epilogue: bf16 score staging -> coalesced writes + per-row tile-min index.
// ---------------------------------------------------------------------------
#define CH_STRIDE 144                    // 128B data + 16B pad, conflict-free
#define CH_MAT   (128 * CH_STRIDE)       // 18432 per matrix per chunk
#define CH_BUF   (2 * CH_MAT)            // A+B per chunk
#define SM_TOTAL (2 * CH_BUF)            // 73728 -> 2 CTAs/SM
#define SC_STRIDE 272                    // score staging row stride (bytes)
#define SM_ROWMIN 36864                  // rowmin array offset (after staging)

__global__ __launch_bounds__(256, 2) void vq_gemm_kernel(float* __restrict__ out) {
    extern __shared__ char smem[];
    const uint32_t sb = smem_u32(smem);
    const int tid = threadIdx.x;
    const int lane = tid & 31;
    const int wid = tid >> 5;
    const int wm = wid & 1;          // warp row (2 x 64)
    const int wn = wid >> 1;         // warp col (4 x 32)
    const int row0 = blockIdx.y * 128;
    const int col0 = blockIdx.x * 128;
    unsigned* rowmin = (unsigned*)(smem + SM_ROWMIN);

    const char* asrc = (const char*)(g_hbf + (size_t)row0 * HID);
    const char* bsrc = (const char*)(g_cbf + (size_t)col0 * HID);

    const int lr = tid >> 3;
    const int lc = tid & 7;
    auto load_chunk = [&](int ck, int buf) {
        const uint32_t bA = sb + buf * CH_BUF;
        const uint32_t bB = bA + CH_MAT;
        const int goff = ck * 128 + lc * 16;
#pragma unroll
        for (int i = 0; i < 4; ++i) {
            int r = lr + i * 32;
            cp16(bA + r * CH_STRIDE + lc * 16, asrc + r * 512 + goff);
            cp16(bB + r * CH_STRIDE + lc * 16, bsrc + r * 512 + goff);
        }
    };

    load_chunk(0, 0); CP_COMMIT();
    load_chunk(1, 1); CP_COMMIT();

    // --- zero this CTA's 128x128 output chunk; drains under the mainloop ---
    {
        float* obase = out + (size_t)row0 * NCODES + col0;
        const uint4 z = make_uint4(0, 0, 0, 0);
#pragma unroll
        for (int i = 0; i < 16; ++i) {
            int idx = tid + i * 256;
            int r = idx >> 5, c = idx & 31;
            st16_cs(obase + (size_t)r * NCODES + c * 4, z);
        }
    }

    float acc[4][4][4];
#pragma unroll
    for (int mi = 0; mi < 4; ++mi)
#pragma unroll
        for (int ni = 0; ni < 4; ++ni)
#pragma unroll
            for (int q = 0; q < 4; ++q) acc[mi][ni][q] = 0.f;

    const int lrow = lane & 15;
    const int lkc  = lane >> 4;

#pragma unroll
    for (int ck = 0; ck < 4; ++ck) {
        if (ck < 3) CP_WAIT1(); else CP_WAIT0();
        __syncthreads();

        const uint32_t bufb = sb + (ck & 1) * CH_BUF;
        const uint32_t aAddr0 = bufb + (wm * 64 + lrow) * CH_STRIDE + lkc * 16;
        const uint32_t bAddr0 = bufb + CH_MAT + (wn * 32 + lrow) * CH_STRIDE + lkc * 16;
#pragma unroll
        for (int ks = 0; ks < 4; ++ks) {
            const uint32_t koff = (uint32_t)ks * 32;
            uint32_t a[4][4], b[2][4];
#pragma unroll
            for (int mi = 0; mi < 4; ++mi)
                LDSM_X4(a[mi][0], a[mi][1], a[mi][2], a[mi][3],
                        aAddr0 + mi * 16 * CH_STRIDE + koff);
#pragma unroll
            for (int nj = 0; nj < 2; ++nj)
                LDSM_X4(b[nj][0], b[nj][1], b[nj][2], b[nj][3],
                        bAddr0 + nj * 16 * CH_STRIDE + koff);
#pragma unroll
            for (int mi = 0; mi < 4; ++mi) {
#pragma unroll
                for (int nj = 0; nj < 2; ++nj) {
                    MMA16816(acc[mi][2 * nj],     a[mi][0], a[mi][1], a[mi][2], a[mi][3],
                             b[nj][0], b[nj][2]);
                    MMA16816(acc[mi][2 * nj + 1], a[mi][0], a[mi][1], a[mi][2], a[mi][3],
                             b[nj][1], b[nj][3]);
                }
            }
        }

        if (ck < 2) {
            __syncthreads();
            load_chunk(ck + 2, ck & 1);
            CP_COMMIT();
        }
    }
    __syncthreads();  // done with chunk buffers — reuse smem for staging/rowmin
    if (tid < 128) rowmin[tid] = 0xFFFFFFFFu;
    __syncthreads();

    // --- Epilogue: score = csq - 2*dot (in place) ---
    float2 csq2[4];
#pragma unroll
    for (int ni = 0; ni < 4; ++ni)
        csq2[ni] = *(const float2*)&g_csq[col0 + wn * 32 + ni * 8 + 2 * (lane & 3)];
#pragma unroll
    for (int mi = 0; mi < 4; ++mi)
#pragma unroll
        for (int ni = 0; ni < 4; ++ni) {
            acc[mi][ni][0] = csq2[ni].x - 2.0f * acc[mi][ni][0];
            acc[mi][ni][1] = csq2[ni].y - 2.0f * acc[mi][ni][1];
            acc[mi][ni][2] = csq2[ni].x - 2.0f * acc[mi][ni][2];
            acc[mi][ni][3] = csq2[ni].y - 2.0f * acc[mi][ni][3];
        }

    // per-row min across warp's 32 cols (quad shuffle) -> smem atomicMin
#pragma unroll
    for (int mi = 0; mi < 4; ++mi)
#pragma unroll
        for (int hh = 0; hh < 2; ++hh) {
            float m = acc[mi][0][2 * hh];
#pragma unroll
            for (int ni = 0; ni < 4; ++ni) {
                m = fminf(m, acc[mi][ni][2 * hh]);
                m = fminf(m, acc[mi][ni][2 * hh + 1]);
            }
            m = fminf(m, __shfl_xor_sync(0xFFFFFFFFu, m, 1));
            m = fminf(m, __shfl_xor_sync(0xFFFFFFFFu, m, 2));
            if ((lane & 3) == 0)
                atomicMin(&rowmin[wm * 64 + mi * 16 + (lane >> 2) + hh * 8], enc_f(m));
        }

    // --- stage bf16 scores in smem ---
    const int erow = wm * 64 + (lane >> 2);
    const int ecol = wn * 32 + 2 * (lane & 3);
#pragma unroll
    for (int mi = 0; mi < 4; ++mi) {
#pragma unroll
        for (int ni = 0; ni < 4; ++ni) {
            __nv_bfloat162 p01 = __floats2bfloat162_rn(acc[mi][ni][0], acc[mi][ni][1]);
            __nv_bfloat162 p23 = __floats2bfloat162_rn(acc[mi][ni][2], acc[mi][ni][3]);
            int r = erow + mi * 16;
            int cbyte = (ecol + ni * 8) * 2;
            *(uint32_t*)(smem + r * SC_STRIDE + cbyte) =
                *reinterpret_cast<uint32_t*>(&p01);
            *(uint32_t*)(smem + (r + 8) * SC_STRIDE + cbyte) =
                *reinterpret_cast<uint32_t*>(&p23);
        }
    }
    __syncthreads();

    // --- Coalesced copy-out: 128 rows x 256B + tile-min index ([row][tile]) ---
#pragma unroll
    for (int i = 0; i < 8; ++i) {
        int idx = tid + i * 256;
        int r = idx >> 4, q = idx & 15;
        uint4 v = *(const uint4*)(smem + r * SC_STRIDE + q * 16);
        *(uint4*)(g_score + (size_t)(row0 + r) * NCODES + col0 + q * 8) = v;
    }
    if (tid < 128)
        g_tmin[(size_t)(row0 + tid) * NTILE + blockIdx.x] = dec_f(rowmin[tid]);
}

// ---------------------------------------------------------------------------
// Select: one block per row. Tile-min scan -> qualifying tiles -> candidates
// -> exact fp32 rescore -> hot store + loss. (Output pre-zeroed by GEMM.)
// ---------------------------------------------------------------------------
__global__ __launch_bounds__(256) void select_kernel(const float* __restrict__ h,
                                                     const float* __restrict__ cbp,
                                                     float* __restrict__ out) {
    const int row = blockIdx.x;
    const int tid = threadIdx.x;
    const int wid = tid >> 5;
    const int lane = tid & 31;
    const unsigned FULL = 0xFFFFFFFFu;

    __shared__ float sh[HID];
    __shared__ float stmin[NTILE];
    __shared__ float sthr;
    __shared__ int scand[MAXC];
    __shared__ int scnt;
    __shared__ unsigned long long skey;
    __shared__ unsigned sidx;

    if (tid == 0) { scnt = 0; skey = 0xFFFFFFFFFFFFFFFFull; }
    sh[tid] = h[(size_t)row * HID + tid];
    if (tid < NTILE) stmin[tid] = g_tmin[(size_t)row * NTILE + tid];  // coalesced
    __syncthreads();

    if (wid == 0) {
        float m = fminf(stmin[lane], stmin[lane + 32]);
#pragma unroll
        for (int o = 16; o; o >>= 1) m = fminf(m, __shfl_xor_sync(FULL, m, o));
        if (lane == 0) sthr = m + EPS;
    }
    __syncthreads();
    const float thr = sthr;

    // scan only qualifying tiles (expected ~1-2)
    for (int t = wid; t < NTILE; t += 8) {
        if (stmin[t] < thr) {
            const __nv_bfloat162* sp =
                (const __nv_bfloat162*)(g_score + (size_t)row * NCODES + t * 128);
#pragma unroll
            for (int q = 0; q < 2; ++q) {
                float2 f = __bfloat1622float2(sp[lane * 2 + q]);
                if (f.x < thr) { int p = atomicAdd(&scnt, 1); if (p < MAXC) scand[p] = t * 128 + lane * 4 + q * 2; }
                if (f.y < thr) { int p = atomicAdd(&scnt, 1); if (p < MAXC) scand[p] = t * 128 + lane * 4 + q * 2 + 1; }
            }
        }
    }
    __syncthreads();

    const float hsq = g_hsq[row];
    const int nc = min(scnt, MAXC);
    for (int ci = wid; ci < nc; ci += 8) {
        int c = scand[ci];
        const float* cp = cbp + (size_t)c * HID;
        float dot = 0.f;
#pragma unroll
        for (int k = lane; k < HID; k += 32) dot = fmaf(sh[k], cp[k], dot);
#pragma unroll
        for (int o = 16; o; o >>= 1) dot += __shfl_xor_sync(FULL, dot, o);
        if (lane == 0) {
            float s = __fadd_rn(__fsub_rn(hsq, __fmul_rn(2.0f, dot)), g_csq[c]);
            atomicMin(&skey, ((u64)enc_f(s) << 32) | (unsigned)c);
        }
    }
    __syncthreads();
    if (tid == 0) sidx = (unsigned)(skey & 0xFFFFFFFFull);
    __syncthreads();
    const unsigned idx = sidx;

    // --- hot store (rest pre-zeroed by the GEMM) + loss ---
    if (tid == 0) out[(size_t)row * NCODES + idx] = 1.0f;

    if (wid == 0) {
        const float* cp = cbp + (size_t)idx * HID;
        float s = 0.f;
#pragma unroll
        for (int k = lane; k < HID; k += 32) {
            float d = sh[k] - cp[k];
            s = fmaf(d, d, s);
        }
#pragma unroll
        for (int o = 16; o; o >>= 1) s += __shfl_xor_sync(FULL, s, o);
        if (lane == 0) {
            float m = s * (1.0f / (float)HID);
            out[(size_t)NROWS * NCODES + row] = __fadd_rn(m, __fmul_rn(0.25f, m));
        }
    }
}

// ---------------------------------------------------------------------------
extern "C" void kernel_launch(void* const* d_in, const int* in_sizes, int n_in,
                              void* d_out, int out_size) {
    const float* h  = (const float*)d_in[0];   // (8192, 256)
    const float* cb = (const float*)d_in[2];   // (8192, 256)
    float* out = (float*)d_out;

    static bool attr_set = false;
    if (!attr_set) {
        cudaFuncSetAttribute(vq_gemm_kernel,
                             cudaFuncAttributeMaxDynamicSharedMemorySize, SM_TOTAL);
        attr_set = true;
    }

    convert_norms_kernel<<<(NROWS + NCODES) / 8, 256>>>(h, cb);

    dim3 grid(NCODES / 128, NROWS / 128);  // (64, 64)
    vq_gemm_kernel<<<grid, 256, SM_TOTAL>>>(out);

    select_kernel<<<NROWS, 256>>>(h, cb, out);
}

// round 17
// speedup vs baseline: 1.1807x; 1.0442x over previous
#include <cuda_runtime.h>
#include <cuda_bf16.h>
#include <cstdint>

#define NROWS 8192
#define NCODES 8192
#define HID 256
#define EPS 1.0f
#define MAXC 256
#define NTILE 64                      // NCODES / 128

typedef unsigned long long u64;

// ---------------------------------------------------------------------------
// Device scratch (static globals — allocation-free)
// ---------------------------------------------------------------------------
__device__ __align__(16) __nv_bfloat16 g_hbf[NROWS * HID];
__device__ __align__(16) __nv_bfloat16 g_cbf[NCODES * HID];
__device__ float g_hsq[NROWS];
__device__ float g_csq[NCODES];
__device__ __align__(16) __nv_bfloat16 g_score[(size_t)NROWS * NCODES];  // 128 MB
__device__ __align__(16) float g_tmin[(size_t)NROWS * NTILE];            // 2 MB, [row][tile]

__device__ __forceinline__ uint32_t smem_u32(const void* p) {
    uint32_t a;
    asm("{ .reg .u64 t; cvta.to.shared.u64 t, %1; cvt.u32.u64 %0, t; }"
        : "=r"(a) : "l"(p));
    return a;
}
__device__ __forceinline__ void cp16(uint32_t dst, const void* src) {
    asm volatile("cp.async.cg.shared.global [%0], [%1], 16;" :: "r"(dst), "l"(src));
}
#define CP_COMMIT() asm volatile("cp.async.commit_group;" ::: "memory")
#define CP_WAIT0()  asm volatile("cp.async.wait_group 0;"  ::: "memory")
#define CP_WAIT1()  asm volatile("cp.async.wait_group 1;"  ::: "memory")

// streaming store (evict-first): 16B
__device__ __forceinline__ void st16_cs(void* p, uint4 v) {
    asm volatile("st.global.cs.v4.u32 [%0], {%1,%2,%3,%4};"
                 :: "l"(p), "r"(v.x), "r"(v.y), "r"(v.z), "r"(v.w) : "memory");
}

#define LDSM_X4(r0, r1, r2, r3, addr)                                          \
    asm volatile("ldmatrix.sync.aligned.m8n8.x4.shared.b16 {%0,%1,%2,%3}, [%4];" \
                 : "=r"(r0), "=r"(r1), "=r"(r2), "=r"(r3) : "r"(addr))

#define MMA16816(d, a0, a1, a2, a3, b0, b1)                                    \
    asm volatile(                                                              \
        "mma.sync.aligned.m16n8k16.row.col.f32.bf16.bf16.f32 "                 \
        "{%0,%1,%2,%3}, {%4,%5,%6,%7}, {%8,%9}, {%0,%1,%2,%3};"                \
        : "+f"((d)[0]), "+f"((d)[1]), "+f"((d)[2]), "+f"((d)[3])               \
        : "r"(a0), "r"(a1), "r"(a2), "r"(a3), "r"(b0), "r"(b1))

// order-preserving float<->uint map
__device__ __forceinline__ unsigned enc_f(float f) {
    unsigned u = __float_as_uint(f);
    return (u & 0x80000000u) ? ~u : (u | 0x80000000u);
}
__device__ __forceinline__ float dec_f(unsigned e) {
    unsigned u = (e & 0x80000000u) ? (e ^ 0x80000000u) : ~e;
    return __uint_as_float(u);
}

// ---------------------------------------------------------------------------
// Fused fp32->bf16 convert + squared norms (one warp per row)
// ---------------------------------------------------------------------------
__global__ void convert_norms_kernel(const float* __restrict__ h,
                                     const float* __restrict__ cb) {
    int warp = (blockIdx.x * blockDim.x + threadIdx.x) >> 5;
    int lane = threadIdx.x & 31;
    const float* src;
    __nv_bfloat16* dst;
    float* nrm;
    if (warp < NROWS) {
        src = h + (size_t)warp * HID; dst = g_hbf + (size_t)warp * HID; nrm = &g_hsq[warp];
    } else {
        src = cb + (size_t)(warp - NROWS) * HID;
        dst = g_cbf + (size_t)(warp - NROWS) * HID;
        nrm = &g_csq[warp - NROWS];
    }
    float s = 0.f;
#pragma unroll
    for (int half2i = 0; half2i < 2; ++half2i) {
        float4 a = ((const float4*)src)[lane + half2i * 32];
        s = fmaf(a.x, a.x, s); s = fmaf(a.y, a.y, s);
        s = fmaf(a.z, a.z, s); s = fmaf(a.w, a.w, s);
        __nv_bfloat162 p0 = __floats2bfloat162_rn(a.x, a.y);
        __nv_bfloat162 p1 = __floats2bfloat162_rn(a.z, a.w);
        uint2 w;
        w.x = *reinterpret_cast<uint32_t*>(&p0);
        w.y = *reinterpret_cast<uint32_t*>(&p1);
        ((uint2*)dst)[lane + half2i * 32] = w;
    }
#pragma unroll
    for (int o = 16; o; o >>= 1) s += __shfl_xor_sync(0xFFFFFFFFu, s, o);
    if (lane == 0) *nrm = s;
}

// ---------------------------------------------------------------------------
// bf16 HMMA GEMM: 128x128 tile per CTA (4096 CTAs), OCCUPANCY 2.
// K chunked 4x64, double-buffered cp.async.
// Output-zeroing spread across the mainloop (4 .cs stores/thread per chunk,
// issued after each chunk's MMAs when the LSU queue is drained).
// Epilogue: bf16 score staging -> .cs coalesced writes + per-row tile-min.
// ---------------------------------------------------------------------------
#define CH_STRIDE 144                    // 128B data + 16B pad, conflict-free
#define CH_MAT   (128 * CH_STRIDE)       // 18432 per matrix per chunk
#define CH_BUF   (2 * CH_MAT)            // A+B per chunk
#define SM_TOTAL (2 * CH_BUF)            // 73728 -> 2 CTAs/SM
#define SC_STRIDE 272                    // score staging row stride (bytes)
#define SM_ROWMIN 36864                  // rowmin array offset (after staging)

__global__ __launch_bounds__(256, 2) void vq_gemm_kernel(float* __restrict__ out) {
    extern __shared__ char smem[];
    const uint32_t sb = smem_u32(smem);
    const int tid = threadIdx.x;
    const int lane = tid & 31;
    const int wid = tid >> 5;
    const int wm = wid & 1;          // warp row (2 x 64)
    const int wn = wid >> 1;         // warp col (4 x 32)
    const int row0 = blockIdx.y * 128;
    const int col0 = blockIdx.x * 128;
    unsigned* rowmin = (unsigned*)(smem + SM_ROWMIN);

    const char* asrc = (const char*)(g_hbf + (size_t)row0 * HID);
    const char* bsrc = (const char*)(g_cbf + (size_t)col0 * HID);
    float* obase = out + (size_t)row0 * NCODES + col0;

    const int lr = tid >> 3;
    const int lc = tid & 7;
    auto load_chunk = [&](int ck, int buf) {
        const uint32_t bA = sb + buf * CH_BUF;
        const uint32_t bB = bA + CH_MAT;
        const int goff = ck * 128 + lc * 16;
#pragma unroll
        for (int i = 0; i < 4; ++i) {
            int r = lr + i * 32;
            cp16(bA + r * CH_STRIDE + lc * 16, asrc + r * 512 + goff);
            cp16(bB + r * CH_STRIDE + lc * 16, bsrc + r * 512 + goff);
        }
    };

    load_chunk(0, 0); CP_COMMIT();
    load_chunk(1, 1); CP_COMMIT();

    float acc[4][4][4];
#pragma unroll
    for (int mi = 0; mi < 4; ++mi)
#pragma unroll
        for (int ni = 0; ni < 4; ++ni)
#pragma unroll
            for (int q = 0; q < 4; ++q) acc[mi][ni][q] = 0.f;

    const int lrow = lane & 15;
    const int lkc  = lane >> 4;

#pragma unroll
    for (int ck = 0; ck < 4; ++ck) {
        if (ck < 3) CP_WAIT1(); else CP_WAIT0();
        __syncthreads();

        const uint32_t bufb = sb + (ck & 1) * CH_BUF;
        const uint32_t aAddr0 = bufb + (wm * 64 + lrow) * CH_STRIDE + lkc * 16;
        const uint32_t bAddr0 = bufb + CH_MAT + (wn * 32 + lrow) * CH_STRIDE + lkc * 16;
#pragma unroll
        for (int ks = 0; ks < 4; ++ks) {
            const uint32_t koff = (uint32_t)ks * 32;
            uint32_t a[4][4], b[2][4];
#pragma unroll
            for (int mi = 0; mi < 4; ++mi)
                LDSM_X4(a[mi][0], a[mi][1], a[mi][2], a[mi][3],
                        aAddr0 + mi * 16 * CH_STRIDE + koff);
#pragma unroll
            for (int nj = 0; nj < 2; ++nj)
                LDSM_X4(b[nj][0], b[nj][1], b[nj][2], b[nj][3],
                        bAddr0 + nj * 16 * CH_STRIDE + koff);
#pragma unroll
            for (int mi = 0; mi < 4; ++mi) {
#pragma unroll
                for (int nj = 0; nj < 2; ++nj) {
                    MMA16816(acc[mi][2 * nj],     a[mi][0], a[mi][1], a[mi][2], a[mi][3],
                             b[nj][0], b[nj][2]);
                    MMA16816(acc[mi][2 * nj + 1], a[mi][0], a[mi][1], a[mi][2], a[mi][3],
                             b[nj][1], b[nj][3]);
                }
            }
        }

        // --- spread zeroing: 4 .cs stores/thread per chunk, LSU now idle ---
        {
            const uint4 z = make_uint4(0, 0, 0, 0);
#pragma unroll
            for (int i = 0; i < 4; ++i) {
                int idx = tid + (ck * 4 + i) * 256;
                int r = idx >> 5, c = idx & 31;
                st16_cs(obase + (size_t)r * NCODES + c * 4, z);
            }
        }

        if (ck < 2) {
            __syncthreads();
            load_chunk(ck + 2, ck & 1);
            CP_COMMIT();
        }
    }
    __syncthreads();  // done with chunk buffers — reuse smem for staging/rowmin
    if (tid < 128) rowmin[tid] = 0xFFFFFFFFu;
    __syncthreads();

    // --- Epilogue: score = csq - 2*dot (in place) ---
    float2 csq2[4];
#pragma unroll
    for (int ni = 0; ni < 4; ++ni)
        csq2[ni] = *(const float2*)&g_csq[col0 + wn * 32 + ni * 8 + 2 * (lane & 3)];
#pragma unroll
    for (int mi = 0; mi < 4; ++mi)
#pragma unroll
        for (int ni = 0; ni < 4; ++ni) {
            acc[mi][ni][0] = csq2[ni].x - 2.0f * acc[mi][ni][0];
            acc[mi][ni][1] = csq2[ni].y - 2.0f * acc[mi][ni][1];
            acc[mi][ni][2] = csq2[ni].x - 2.0f * acc[mi][ni][2];
            acc[mi][ni][3] = csq2[ni].y - 2.0f * acc[mi][ni][3];
        }

    // per-row min across warp's 32 cols (quad shuffle) -> smem atomicMin
#pragma unroll
    for (int mi = 0; mi < 4; ++mi)
#pragma unroll
        for (int hh = 0; hh < 2; ++hh) {
            float m = acc[mi][0][2 * hh];
#pragma unroll
            for (int ni = 0; ni < 4; ++ni) {
                m = fminf(m, acc[mi][ni][2 * hh]);
                m = fminf(m, acc[mi][ni][2 * hh + 1]);
            }
            m = fminf(m, __shfl_xor_sync(0xFFFFFFFFu, m, 1));
            m = fminf(m, __shfl_xor_sync(0xFFFFFFFFu, m, 2));
            if ((lane & 3) == 0)
                atomicMin(&rowmin[wm * 64 + mi * 16 + (lane >> 2) + hh * 8], enc_f(m));
        }

    // --- stage bf16 scores in smem ---
    const int erow = wm * 64 + (lane >> 2);
    const int ecol = wn * 32 + 2 * (lane & 3);
#pragma unroll
    for (int mi = 0; mi < 4; ++mi) {
#pragma unroll
        for (int ni = 0; ni < 4; ++ni) {
            __nv_bfloat162 p01 = __floats2bfloat162_rn(acc[mi][ni][0], acc[mi][ni][1]);
            __nv_bfloat162 p23 = __floats2bfloat162_rn(acc[mi][ni][2], acc[mi][ni][3]);
            int r = erow + mi * 16;
            int cbyte = (ecol + ni * 8) * 2;
            *(uint32_t*)(smem + r * SC_STRIDE + cbyte) =
                *reinterpret_cast<uint32_t*>(&p01);
            *(uint32_t*)(smem + (r + 8) * SC_STRIDE + cbyte) =
                *reinterpret_cast<uint32_t*>(&p23);
        }
    }
    __syncthreads();

    // --- Coalesced .cs copy-out: 128 rows x 256B + tile-min index ---
#pragma unroll
    for (int i = 0; i < 8; ++i) {
        int idx = tid + i * 256;
        int r = idx >> 4, q = idx & 15;
        uint4 v = *(const uint4*)(smem + r * SC_STRIDE + q * 16);
        st16_cs(g_score + (size_t)(row0 + r) * NCODES + col0 + q * 8, v);
    }
    if (tid < 128)
        g_tmin[(size_t)(row0 + tid) * NTILE + blockIdx.x] = dec_f(rowmin[tid]);
}

// ---------------------------------------------------------------------------
// Select: one block per row. Tile-min scan -> qualifying tiles -> candidates
// -> exact fp32 rescore -> hot store + loss. (Output pre-zeroed by GEMM.)
// ---------------------------------------------------------------------------
__global__ __launch_bounds__(256) void select_kernel(const float* __restrict__ h,
                                                     const float* __restrict__ cbp,
                                                     float* __restrict__ out) {
    const int row = blockIdx.x;
    const int tid = threadIdx.x;
    const int wid = tid >> 5;
    const int lane = tid & 31;
    const unsigned FULL = 0xFFFFFFFFu;

    __shared__ float sh[HID];
    __shared__ float stmin[NTILE];
    __shared__ float sthr;
    __shared__ int scand[MAXC];
    __shared__ int scnt;
    __shared__ unsigned long long skey;
    __shared__ unsigned sidx;

    if (tid == 0) { scnt = 0; skey = 0xFFFFFFFFFFFFFFFFull; }
    sh[tid] = h[(size_t)row * HID + tid];
    if (tid < NTILE) stmin[tid] = g_tmin[(size_t)row * NTILE + tid];  // coalesced
    __syncthreads();

    if (wid == 0) {
        float m = fminf(stmin[lane], stmin[lane + 32]);
#pragma unroll
        for (int o = 16; o; o >>= 1) m = fminf(m, __shfl_xor_sync(FULL, m, o));
        if (lane == 0) sthr = m + EPS;
    }
    __syncthreads();
    const float thr = sthr;

    // scan only qualifying tiles (expected ~1-2)
    for (int t = wid; t < NTILE; t += 8) {
        if (stmin[t] < thr) {
            const __nv_bfloat162* sp =
                (const __nv_bfloat162*)(g_score + (size_t)row * NCODES + t * 128);
#pragma unroll
            for (int q = 0; q < 2; ++q) {
                float2 f = __bfloat1622float2(sp[lane * 2 + q]);
                if (f.x < thr) { int p = atomicAdd(&scnt, 1); if (p < MAXC) scand[p] = t * 128 + lane * 4 + q * 2; }
                if (f.y < thr) { int p = atomicAdd(&scnt, 1); if (p < MAXC) scand[p] = t * 128 + lane * 4 + q * 2 + 1; }
            }
        }
    }
    __syncthreads();

    const float hsq = g_hsq[row];
    const int nc = min(scnt, MAXC);
    for (int ci = wid; ci < nc; ci += 8) {
        int c = scand[ci];
        const float* cp = cbp + (size_t)c * HID;
        float dot = 0.f;
#pragma unroll
        for (int k = lane; k < HID; k += 32) dot = fmaf(sh[k], cp[k], dot);
#pragma unroll
        for (int o = 16; o; o >>= 1) dot += __shfl_xor_sync(FULL, dot, o);
        if (lane == 0) {
            float s = __fadd_rn(__fsub_rn(hsq, __fmul_rn(2.0f, dot)), g_csq[c]);
            atomicMin(&skey, ((u64)enc_f(s) << 32) | (unsigned)c);
        }
    }
    __syncthreads();
    if (tid == 0) sidx = (unsigned)(skey & 0xFFFFFFFFull);
    __syncthreads();
    const unsigned idx = sidx;

    // --- hot store (rest pre-zeroed by the GEMM) + loss ---
    if (tid == 0) out[(size_t)row * NCODES + idx] = 1.0f;

    if (wid == 0) {
        const float* cp = cbp + (size_t)idx * HID;
        float s = 0.f;
#pragma unroll
        for (int k = lane; k < HID; k += 32) {
            float d = sh[k] - cp[k];
            s = fmaf(d, d, s);
        }
#pragma unroll
        for (int o = 16; o; o >>= 1) s += __shfl_xor_sync(FULL, s, o);
        if (lane == 0) {
            float m = s * (1.0f / (float)HID);
            out[(size_t)NROWS * NCODES + row] = __fadd_rn(m, __fmul_rn(0.25f, m));
        }
    }
}

// ---------------------------------------------------------------------------
extern "C" void kernel_launch(void* const* d_in, const int* in_sizes, int n_in,
                              void* d_out, int out_size) {
    const float* h  = (const float*)d_in[0];   // (8192, 256)
    const float* cb = (const float*)d_in[2];   // (8192, 256)
    float* out = (float*)d_out;

    static bool attr_set = false;
    if (!attr_set) {
        cudaFuncSetAttribute(vq_gemm_kernel,
                             cudaFuncAttributeMaxDynamicSharedMemorySize, SM_TOTAL);
        attr_set = true;
    }

    convert_norms_kernel<<<(NROWS + NCODES) / 8, 256>>>(h, cb);

    dim3 grid(NCODES / 128, NROWS / 128);  // (64, 64)
    vq_gemm_kernel<<<grid, 256, SM_TOTAL>>>(out);

    select_kernel<<<NROWS, 256>>>(h, cb, out);
}